// round 1
// baseline (speedup 1.0000x reference)
#include <cuda_runtime.h>
#include <cuda_bf16.h>
#include <math.h>

// Shapes
#define Bn 256
#define Sn 128
#define Dn 768
#define K2 1536           // 2*D
#define MASK_ID 103

// Scratch (no allocs allowed -> __device__ globals)
__device__ float g_feats[Bn * K2];   // [att(768), mask_logits(768)] per batch
__device__ float g_h[Bn * Dn];       // tanh dense output

// LABEL_IDS flattened: groups of 8, 6, 7
static __device__ const int c_ids[21] = {
    2307, 2204, 3835, 2157, 6581, 2986, 5151, 3893,
    7929, 24791, 8699, 4257, 16021, 6623,
    6659, 2919, 11771, 3532, 11325, 4997, 13135
};

// ---------------------------------------------------------------------------
// Kernel A: per-batch mask find, category head, masked softmax attention pool.
// One block per batch row, 256 threads.
// ---------------------------------------------------------------------------
__global__ __launch_bounds__(256) void kA(
    const float* __restrict__ bert,     // [B,S,D]
    const int*   __restrict__ ids,      // [B,S]
    const int*   __restrict__ length,   // [B]
    const float* __restrict__ senti_w,  // [2,D]
    const float* __restrict__ senti_b,  // [2]
    float*       __restrict__ out)      // category at out[0 .. 2B)
{
    const int b = blockIdx.x;
    const int t = threadIdx.x;
    const int warp = t >> 5, lane = t & 31;

    __shared__ float ml[Dn];       // mask_logits
    __shared__ float sc[Sn];       // scores
    __shared__ int   mp_s;
    __shared__ float red0;

    const float* X = bert + (size_t)b * Sn * Dn;

    if (t < Sn) {
        sc[t] = -INFINITY;
        if (ids[b * Sn + t] == MASK_ID) mp_s = t;   // exactly one match
    }
    __syncthreads();
    const int mp  = mp_s;
    const int len = length[b];

    // mask_logits -> smem
    for (int d = t; d < Dn; d += 256) ml[d] = X[mp * Dn + d];
    __syncthreads();

    // category head: warps 0/1 compute the two output classes
    if (warp < 2) {
        float s = 0.f;
        for (int d = lane; d < Dn; d += 32) s += X[d] * senti_w[warp * Dn + d];
        #pragma unroll
        for (int o = 16; o > 0; o >>= 1) s += __shfl_xor_sync(0xffffffffu, s, o);
        if (lane == 0) out[b * 2 + warp] = s + senti_b[warp];
    }

    // scores_raw for valid s in [3, 3+len) only
    for (int s = 3 + warp; s < 3 + len; s += 8) {
        const float* row = X + (size_t)s * Dn;
        float acc = 0.f;
        for (int d = lane; d < Dn; d += 32) acc += row[d] * ml[d];
        #pragma unroll
        for (int o = 16; o > 0; o >>= 1) acc += __shfl_xor_sync(0xffffffffu, acc, o);
        if (lane == 0) sc[s] = acc;
    }
    __syncthreads();

    // softmax: max
    if (t < 32) {
        float m = -INFINITY;
        for (int i = t; i < Sn; i += 32) m = fmaxf(m, sc[i]);
        #pragma unroll
        for (int o = 16; o > 0; o >>= 1) m = fmaxf(m, __shfl_xor_sync(0xffffffffu, m, o));
        if (t == 0) red0 = m;
    }
    __syncthreads();
    const float mx = red0;
    if (t < Sn) {
        float v = sc[t];
        sc[t] = (v == -INFINITY) ? 0.f : __expf(v - mx);
    }
    __syncthreads();
    if (t < 32) {
        float s = 0.f;
        for (int i = t; i < Sn; i += 32) s += sc[i];
        #pragma unroll
        for (int o = 16; o > 0; o >>= 1) s += __shfl_xor_sync(0xffffffffu, s, o);
        if (t == 0) red0 = s;
    }
    __syncthreads();
    const float inv = 1.f / red0;

    // attention pool: thread owns d = t, t+256, t+512
    float a0 = 0.f, a1 = 0.f, a2 = 0.f;
    for (int s = 3; s < 3 + len; ++s) {
        const float w = sc[s];
        const float* row = X + (size_t)s * Dn;
        a0 += w * row[t];
        a1 += w * row[t + 256];
        a2 += w * row[t + 512];
    }
    float* F = g_feats + (size_t)b * K2;
    F[t]           = a0 * inv;
    F[t + 256]     = a1 * inv;
    F[t + 512]     = a2 * inv;
    F[Dn + t]       = ml[t];
    F[Dn + t + 256] = ml[t + 256];
    F[Dn + t + 512] = ml[t + 512];
}

// ---------------------------------------------------------------------------
// Kernel B: h = tanh(feats @ dense_w^T + dense_b)
// A = g_feats [256 x 1536], W = dense_w [768 x 1536] row-major, C -> g_h [256 x 768]
// Tiled fp32: BM=32, BN=64, BK=32, 256 threads, 2x4 micro-tile.
// ---------------------------------------------------------------------------
#define BM 32
#define BN 64
#define BK 32
__global__ __launch_bounds__(256) void kB(
    const float* __restrict__ Wd,   // [768,1536]
    const float* __restrict__ bd)   // [768]
{
    __shared__ float As[BM][BK + 1];
    __shared__ float Ws[BN][BK + 1];

    const int bm = blockIdx.y * BM;
    const int bn = blockIdx.x * BN;
    const int t  = threadIdx.x;
    const int tn = t & 15;        // 0..15 -> 4 n each
    const int tm = t >> 4;        // 0..15 -> 2 m each

    float acc[2][4] = {};

    for (int k0 = 0; k0 < K2; k0 += BK) {
        #pragma unroll
        for (int i = t; i < BM * BK; i += 256) {
            int m = i >> 5, k = i & 31;
            As[m][k] = g_feats[(size_t)(bm + m) * K2 + k0 + k];
        }
        #pragma unroll
        for (int i = t; i < BN * BK; i += 256) {
            int n = i >> 5, k = i & 31;
            Ws[n][k] = Wd[(size_t)(bn + n) * K2 + k0 + k];
        }
        __syncthreads();
        #pragma unroll
        for (int kk = 0; kk < BK; ++kk) {
            const float a0 = As[tm * 2 + 0][kk];
            const float a1 = As[tm * 2 + 1][kk];
            const float b0 = Ws[tn * 4 + 0][kk];
            const float b1 = Ws[tn * 4 + 1][kk];
            const float b2 = Ws[tn * 4 + 2][kk];
            const float b3 = Ws[tn * 4 + 3][kk];
            acc[0][0] += a0 * b0; acc[0][1] += a0 * b1;
            acc[0][2] += a0 * b2; acc[0][3] += a0 * b3;
            acc[1][0] += a1 * b0; acc[1][1] += a1 * b1;
            acc[1][2] += a1 * b2; acc[1][3] += a1 * b3;
        }
        __syncthreads();
    }

    #pragma unroll
    for (int i = 0; i < 2; ++i) {
        const int m = bm + tm * 2 + i;
        #pragma unroll
        for (int j = 0; j < 4; ++j) {
            const int n = bn + tn * 4 + j;
            g_h[(size_t)m * Dn + n] = tanhf(acc[i][j] + bd[n]);
        }
    }
}

// ---------------------------------------------------------------------------
// Kernel C: sparse decoder (21 vocab rows) + label-group mixes.
// One block per batch, 256 threads.
// out layout: category (B*2) then out[b,o,g] (B*2*3) starting at offset 2*B.
// ---------------------------------------------------------------------------
__global__ __launch_bounds__(256) void kC(
    const float* __restrict__ dec_w,   // [V,768]
    const float* __restrict__ dec_b,   // [V]
    const float* __restrict__ w0,      // [2,8]
    const float* __restrict__ w1,      // [2,6]
    const float* __restrict__ w2,      // [2,7]
    float*       __restrict__ out)
{
    const int b = blockIdx.x;
    const int t = threadIdx.x;
    const int warp = t >> 5, lane = t & 31;

    __shared__ float hs[Dn];
    __shared__ float probs[21];

    for (int d = t; d < Dn; d += 256) hs[d] = g_h[(size_t)b * Dn + d];
    __syncthreads();

    for (int j = warp; j < 21; j += 8) {
        const int v = c_ids[j];
        const float* row = dec_w + (size_t)v * Dn;
        float s = 0.f;
        for (int d = lane; d < Dn; d += 32) s += hs[d] * row[d];
        #pragma unroll
        for (int o = 16; o > 0; o >>= 1) s += __shfl_xor_sync(0xffffffffu, s, o);
        if (lane == 0) probs[j] = tanhf(s + dec_b[v]);
    }
    __syncthreads();

    if (t < 6) {
        const int o = t / 3, g = t % 3;
        const float* w = (g == 0) ? w0 : (g == 1) ? w1 : w2;
        const int off = (g == 0) ? 0 : (g == 1) ? 8 : 14;
        const int n   = (g == 0) ? 8 : (g == 1) ? 6 : 7;
        float s = 0.f;
        for (int j = 0; j < n; ++j) s += probs[off + j] * w[o * n + j];
        out[2 * Bn + b * 6 + o * 3 + g] = s;
    }
}

// ---------------------------------------------------------------------------
extern "C" void kernel_launch(void* const* d_in, const int* in_sizes, int n_in,
                              void* d_out, int out_size)
{
    const float* bert    = (const float*)d_in[0];
    const int*   ids     = (const int*)  d_in[1];
    const int*   length  = (const int*)  d_in[2];
    const float* senti_w = (const float*)d_in[3];
    const float* senti_b = (const float*)d_in[4];
    const float* dense_w = (const float*)d_in[5];
    const float* dense_b = (const float*)d_in[6];
    const float* dec_w   = (const float*)d_in[7];
    const float* dec_b   = (const float*)d_in[8];
    const float* w0      = (const float*)d_in[9];
    const float* w1      = (const float*)d_in[10];
    const float* w2      = (const float*)d_in[11];
    float* out = (float*)d_out;

    kA<<<Bn, 256>>>(bert, ids, length, senti_w, senti_b, out);
    kB<<<dim3(Dn / BN, Bn / BM), 256>>>(dense_w, dense_b);
    kC<<<Bn, 256>>>(dec_w, dec_b, w0, w1, w2, out);
}

// round 2
// speedup vs baseline: 1.2623x; 1.2623x over previous
#include <cuda_runtime.h>
#include <cuda_bf16.h>
#include <math.h>

#define Bn 256
#define Sn 128
#define Dn 768
#define K2 1536
#define MASK_ID 103
#define KSPLIT 4
#define KCH (K2 / KSPLIT)   // 384

// Scratch (__device__ globals; no allocs allowed)
__device__ float g_ml[Bn * Dn];            // mask_logits per batch
__device__ float g_sc[Bn * Sn];            // raw scores
__device__ float g_feats[Bn * K2];         // [att | mask_logits]
__device__ float g_part[KSPLIT][Bn * Dn];  // split-K partials
__device__ float g_h[Bn * Dn];             // tanh dense output

static __device__ const int c_ids[21] = {
    2307, 2204, 3835, 2157, 6581, 2986, 5151, 3893,
    7929, 24791, 8699, 4257, 16021, 6623,
    6659, 2919, 11771, 3532, 11325, 4997, 13135
};

// ---------------------------------------------------------------------------
// kA0: per-batch mask find, mask_logits copy (to g_ml and feats), category head
// ---------------------------------------------------------------------------
__global__ __launch_bounds__(128) void kA0(
    const float* __restrict__ bert,
    const int*   __restrict__ ids,
    const float* __restrict__ senti_w,
    const float* __restrict__ senti_b,
    float*       __restrict__ out)
{
    const int b = blockIdx.x;
    const int t = threadIdx.x;
    const int warp = t >> 5, lane = t & 31;
    __shared__ int mp_s;

    if (ids[b * Sn + t] == MASK_ID) mp_s = t;
    __syncthreads();
    const int mp = mp_s;
    const float* X = bert + (size_t)b * Sn * Dn;

    // mask_logits -> g_ml and g_feats[.., 768..1536)
    #pragma unroll
    for (int j = 0; j < 6; ++j) {
        const int d = t + j * 128;
        const float v = X[(size_t)mp * Dn + d];
        g_ml[(size_t)b * Dn + d] = v;
        g_feats[(size_t)b * K2 + Dn + d] = v;
    }

    // category head (pooler = row 0)
    if (warp < 2) {
        float s = 0.f;
        for (int d = lane * 4; d < Dn; d += 128) {
            const float4 x = *(const float4*)&X[d];
            const float4 w = *(const float4*)&senti_w[warp * Dn + d];
            s += x.x * w.x + x.y * w.y + x.z * w.z + x.w * w.w;
        }
        #pragma unroll
        for (int o = 16; o > 0; o >>= 1) s += __shfl_xor_sync(0xffffffffu, s, o);
        if (lane == 0) out[b * 2 + warp] = s + senti_b[warp];
    }
}

// ---------------------------------------------------------------------------
// kA1: scores_raw[b,s] = dot(bert[b,s,:], ml[b,:]) for valid rows
// grid (B, 16), 256 thr = 8 warps, one warp per row.
// ---------------------------------------------------------------------------
__global__ __launch_bounds__(256) void kA1(
    const float* __restrict__ bert,
    const int*   __restrict__ length)
{
    const int b = blockIdx.x;
    const int len = length[b];
    const int s0 = blockIdx.y * 8;
    if (s0 >= 3 + len) return;

    const int t = threadIdx.x;
    const int warp = t >> 5, lane = t & 31;

    __shared__ float ml[Dn];
    #pragma unroll
    for (int j = 0; j < 3; ++j) ml[t + j * 256] = g_ml[(size_t)b * Dn + t + j * 256];
    __syncthreads();

    const int s = s0 + warp;
    if (s < 3 || s >= 3 + len) return;

    const float* row = bert + ((size_t)b * Sn + s) * Dn;
    float acc = 0.f;
    #pragma unroll
    for (int j = 0; j < 6; ++j) {
        const int d = j * 128 + lane * 4;
        const float4 x = *(const float4*)&row[d];
        const float4 m = *(const float4*)&ml[d];
        acc += x.x * m.x + x.y * m.y + x.z * m.z + x.w * m.w;
    }
    #pragma unroll
    for (int o = 16; o > 0; o >>= 1) acc += __shfl_xor_sync(0xffffffffu, acc, o);
    if (lane == 0) g_sc[b * Sn + s] = acc;
}

// ---------------------------------------------------------------------------
// kA2: softmax (recomputed per block, tiny) + attention pool.
// grid (B, 6), 128 thr; block handles d-chunk of 128.
// ---------------------------------------------------------------------------
__global__ __launch_bounds__(128) void kA2(
    const float* __restrict__ bert,
    const int*   __restrict__ length)
{
    const int b = blockIdx.x;
    const int t = threadIdx.x;
    const int warp = t >> 5, lane = t & 31;
    const int len = length[b];

    __shared__ float w_sh[112];
    __shared__ float red[4];

    // load raw score for this thread's s (t < len), block-reduce max
    float v = (t < len) ? g_sc[b * Sn + 3 + t] : -INFINITY;
    float m = v;
    #pragma unroll
    for (int o = 16; o > 0; o >>= 1) m = fmaxf(m, __shfl_xor_sync(0xffffffffu, m, o));
    if (lane == 0) red[warp] = m;
    __syncthreads();
    m = fmaxf(fmaxf(red[0], red[1]), fmaxf(red[2], red[3]));

    float e = (t < len) ? __expf(v - m) : 0.f;
    float su = e;
    #pragma unroll
    for (int o = 16; o > 0; o >>= 1) su += __shfl_xor_sync(0xffffffffu, su, o);
    __syncthreads();
    if (lane == 0) red[warp] = su;
    __syncthreads();
    su = red[0] + red[1] + red[2] + red[3];
    if (t < len) w_sh[t] = e / su;
    __syncthreads();

    // pool over valid rows, 4-deep unroll for MLP
    const int d = blockIdx.y * 128 + t;
    const float* Xp = bert + ((size_t)b * Sn + 3) * Dn + d;
    float a0 = 0.f, a1 = 0.f, a2 = 0.f, a3 = 0.f;
    int s = 0;
    const int nn = len & ~3;
    for (; s < nn; s += 4) {
        a0 += w_sh[s]     * Xp[(size_t)(s)     * Dn];
        a1 += w_sh[s + 1] * Xp[(size_t)(s + 1) * Dn];
        a2 += w_sh[s + 2] * Xp[(size_t)(s + 2) * Dn];
        a3 += w_sh[s + 3] * Xp[(size_t)(s + 3) * Dn];
    }
    for (; s < len; ++s) a0 += w_sh[s] * Xp[(size_t)s * Dn];
    g_feats[(size_t)b * K2 + d] = (a0 + a1) + (a2 + a3);
}

// ---------------------------------------------------------------------------
// kB: split-K GEMM partials. C_part[ks] = feats[:, ks*384:(ks+1)*384] @ W^T chunk
// Tile 64x64, BK=16, 256 thr, 4x4 microtile via LDS.128. grid (12, 4, 4).
// ---------------------------------------------------------------------------
__global__ __launch_bounds__(256) void kB(const float* __restrict__ Wd)
{
    __shared__ float As[16][64];
    __shared__ float Ws[16][64];

    const int t  = threadIdx.x;
    const int bm = blockIdx.y * 64;
    const int bn = blockIdx.x * 64;
    const int k0 = blockIdx.z * KCH;

    const int lm = t & 63;        // row for loads
    const int kq = t >> 6;        // 0..3 -> k sub-group of 4
    const int tn = t & 15, tm = t >> 4;

    float acc[4][4] = {};

    for (int kt = 0; kt < KCH; kt += 16) {
        const int kg = k0 + kt + kq * 4;
        const float4 av = *(const float4*)&g_feats[(size_t)(bm + lm) * K2 + kg];
        const float4 wv = *(const float4*)&Wd[(size_t)(bn + lm) * K2 + kg];
        __syncthreads();
        As[kq * 4 + 0][lm] = av.x; As[kq * 4 + 1][lm] = av.y;
        As[kq * 4 + 2][lm] = av.z; As[kq * 4 + 3][lm] = av.w;
        Ws[kq * 4 + 0][lm] = wv.x; Ws[kq * 4 + 1][lm] = wv.y;
        Ws[kq * 4 + 2][lm] = wv.z; Ws[kq * 4 + 3][lm] = wv.w;
        __syncthreads();
        #pragma unroll
        for (int kk = 0; kk < 16; ++kk) {
            const float4 a = *(const float4*)&As[kk][tm * 4];
            const float4 w = *(const float4*)&Ws[kk][tn * 4];
            acc[0][0] += a.x * w.x; acc[0][1] += a.x * w.y; acc[0][2] += a.x * w.z; acc[0][3] += a.x * w.w;
            acc[1][0] += a.y * w.x; acc[1][1] += a.y * w.y; acc[1][2] += a.y * w.z; acc[1][3] += a.y * w.w;
            acc[2][0] += a.z * w.x; acc[2][1] += a.z * w.y; acc[2][2] += a.z * w.z; acc[2][3] += a.z * w.w;
            acc[3][0] += a.w * w.x; acc[3][1] += a.w * w.y; acc[3][2] += a.w * w.z; acc[3][3] += a.w * w.w;
        }
    }

    float* P = g_part[blockIdx.z];
    #pragma unroll
    for (int i = 0; i < 4; ++i) {
        const int m = bm + tm * 4 + i;
        #pragma unroll
        for (int j = 0; j < 4; ++j)
            P[(size_t)m * Dn + bn + tn * 4 + j] = acc[i][j];
    }
}

// kB2: reduce partials + bias + tanh (deterministic order)
__global__ __launch_bounds__(256) void kB2(const float* __restrict__ bd)
{
    const int i = blockIdx.x * 256 + threadIdx.x;   // over Bn*Dn
    const float s = ((g_part[0][i] + g_part[1][i]) + (g_part[2][i] + g_part[3][i]))
                    + bd[i % Dn];
    g_h[i] = tanhf(s);
}

// ---------------------------------------------------------------------------
// kC: 21 sparse decoder rows + label-group mixes
// ---------------------------------------------------------------------------
__global__ __launch_bounds__(256) void kC(
    const float* __restrict__ dec_w,
    const float* __restrict__ dec_b,
    const float* __restrict__ w0,
    const float* __restrict__ w1,
    const float* __restrict__ w2,
    float*       __restrict__ out)
{
    const int b = blockIdx.x;
    const int t = threadIdx.x;
    const int warp = t >> 5, lane = t & 31;

    __shared__ float hs[Dn];
    __shared__ float probs[21];

    #pragma unroll
    for (int j = 0; j < 3; ++j) hs[t + j * 256] = g_h[(size_t)b * Dn + t + j * 256];
    __syncthreads();

    for (int j = warp; j < 21; j += 8) {
        const int v = c_ids[j];
        const float* row = dec_w + (size_t)v * Dn;
        float s = 0.f;
        for (int d = lane * 4; d < Dn; d += 128) {
            const float4 h4 = *(const float4*)&hs[d];
            const float4 r4 = *(const float4*)&row[d];
            s += h4.x * r4.x + h4.y * r4.y + h4.z * r4.z + h4.w * r4.w;
        }
        #pragma unroll
        for (int o = 16; o > 0; o >>= 1) s += __shfl_xor_sync(0xffffffffu, s, o);
        if (lane == 0) probs[j] = tanhf(s + dec_b[v]);
    }
    __syncthreads();

    if (t < 6) {
        const int o = t / 3, g = t % 3;
        const float* w = (g == 0) ? w0 : (g == 1) ? w1 : w2;
        const int off = (g == 0) ? 0 : (g == 1) ? 8 : 14;
        const int n   = (g == 0) ? 8 : (g == 1) ? 6 : 7;
        float s = 0.f;
        for (int j = 0; j < n; ++j) s += probs[off + j] * w[o * n + j];
        out[2 * Bn + b * 6 + o * 3 + g] = s;
    }
}

// ---------------------------------------------------------------------------
extern "C" void kernel_launch(void* const* d_in, const int* in_sizes, int n_in,
                              void* d_out, int out_size)
{
    const float* bert    = (const float*)d_in[0];
    const int*   ids     = (const int*)  d_in[1];
    const int*   length  = (const int*)  d_in[2];
    const float* senti_w = (const float*)d_in[3];
    const float* senti_b = (const float*)d_in[4];
    const float* dense_w = (const float*)d_in[5];
    const float* dense_b = (const float*)d_in[6];
    const float* dec_w   = (const float*)d_in[7];
    const float* dec_b   = (const float*)d_in[8];
    const float* w0      = (const float*)d_in[9];
    const float* w1      = (const float*)d_in[10];
    const float* w2      = (const float*)d_in[11];
    float* out = (float*)d_out;

    kA0<<<Bn, 128>>>(bert, ids, senti_w, senti_b, out);
    kA1<<<dim3(Bn, 16), 256>>>(bert, length);
    kA2<<<dim3(Bn, 6), 128>>>(bert, length);
    kB <<<dim3(Dn / 64, Bn / 64, KSPLIT), 256>>>(dense_w);
    kB2<<<(Bn * Dn) / 256, 256>>>(dense_b);
    kC <<<Bn, 256>>>(dec_w, dec_b, w0, w1, w2, out);
}

// round 3
// speedup vs baseline: 1.8839x; 1.4924x over previous
#include <cuda_runtime.h>
#include <cuda_bf16.h>
#include <math.h>

#define Bn 256
#define Sn 128
#define Dn 768
#define K2 1536
#define MASK_ID 103
#define KSPLIT 8
#define KCH (K2 / KSPLIT)   // 192

// Scratch (__device__ globals; no allocs allowed)
__device__ float g_ml[Bn * Dn];            // mask_logits per batch
__device__ float g_sc[Bn * Sn];            // raw scores
__device__ float g_feats[Bn * K2];         // [att | mask_logits]
__device__ float g_part[KSPLIT][Bn * Dn];  // split-K partials
__device__ float g_h[Bn * Dn];             // tanh dense output

static __device__ const int c_ids[21] = {
    2307, 2204, 3835, 2157, 6581, 2986, 5151, 3893,
    7929, 24791, 8699, 4257, 16021, 6623,
    6659, 2919, 11771, 3532, 11325, 4997, 13135
};

// ---------------------------------------------------------------------------
// kA0: per-batch mask find, mask_logits copy, category head
// ---------------------------------------------------------------------------
__global__ __launch_bounds__(128) void kA0(
    const float* __restrict__ bert,
    const int*   __restrict__ ids,
    const float* __restrict__ senti_w,
    const float* __restrict__ senti_b,
    float*       __restrict__ out)
{
    const int b = blockIdx.x;
    const int t = threadIdx.x;
    const int warp = t >> 5, lane = t & 31;
    __shared__ int mp_s;

    if (ids[b * Sn + t] == MASK_ID) mp_s = t;
    __syncthreads();
    const int mp = mp_s;
    const float* X = bert + (size_t)b * Sn * Dn;

    #pragma unroll
    for (int j = 0; j < 6; ++j) {
        const int d = t + j * 128;
        const float v = X[(size_t)mp * Dn + d];
        g_ml[(size_t)b * Dn + d] = v;
        g_feats[(size_t)b * K2 + Dn + d] = v;
    }

    if (warp < 2) {
        float s = 0.f;
        for (int d = lane * 4; d < Dn; d += 128) {
            const float4 x = *(const float4*)&X[d];
            const float4 w = *(const float4*)&senti_w[warp * Dn + d];
            s += x.x * w.x + x.y * w.y + x.z * w.z + x.w * w.w;
        }
        #pragma unroll
        for (int o = 16; o > 0; o >>= 1) s += __shfl_xor_sync(0xffffffffu, s, o);
        if (lane == 0) out[b * 2 + warp] = s + senti_b[warp];
    }
}

// ---------------------------------------------------------------------------
// kA1: scores_raw[b,s] = dot(bert[b,s,:], ml[b,:]) for valid rows
// ---------------------------------------------------------------------------
__global__ __launch_bounds__(256) void kA1(
    const float* __restrict__ bert,
    const int*   __restrict__ length)
{
    const int b = blockIdx.x;
    const int len = length[b];
    const int s0 = blockIdx.y * 8;
    if (s0 >= 3 + len) return;

    const int t = threadIdx.x;
    const int warp = t >> 5, lane = t & 31;

    __shared__ float ml[Dn];
    #pragma unroll
    for (int j = 0; j < 3; ++j) ml[t + j * 256] = g_ml[(size_t)b * Dn + t + j * 256];
    __syncthreads();

    const int s = s0 + warp;
    if (s < 3 || s >= 3 + len) return;

    const float* row = bert + ((size_t)b * Sn + s) * Dn;
    float acc = 0.f;
    #pragma unroll
    for (int j = 0; j < 6; ++j) {
        const int d = j * 128 + lane * 4;
        const float4 x = *(const float4*)&row[d];
        const float4 m = *(const float4*)&ml[d];
        acc += x.x * m.x + x.y * m.y + x.z * m.z + x.w * m.w;
    }
    #pragma unroll
    for (int o = 16; o > 0; o >>= 1) acc += __shfl_xor_sync(0xffffffffu, acc, o);
    if (lane == 0) g_sc[b * Sn + s] = acc;
}

// ---------------------------------------------------------------------------
// kA2: softmax (tiny, recomputed) + attention pool
// ---------------------------------------------------------------------------
__global__ __launch_bounds__(128) void kA2(
    const float* __restrict__ bert,
    const int*   __restrict__ length)
{
    const int b = blockIdx.x;
    const int t = threadIdx.x;
    const int warp = t >> 5, lane = t & 31;
    const int len = length[b];

    __shared__ float w_sh[112];
    __shared__ float red[4];

    float v = (t < len) ? g_sc[b * Sn + 3 + t] : -INFINITY;
    float m = v;
    #pragma unroll
    for (int o = 16; o > 0; o >>= 1) m = fmaxf(m, __shfl_xor_sync(0xffffffffu, m, o));
    if (lane == 0) red[warp] = m;
    __syncthreads();
    m = fmaxf(fmaxf(red[0], red[1]), fmaxf(red[2], red[3]));

    float e = (t < len) ? __expf(v - m) : 0.f;
    float su = e;
    #pragma unroll
    for (int o = 16; o > 0; o >>= 1) su += __shfl_xor_sync(0xffffffffu, su, o);
    __syncthreads();
    if (lane == 0) red[warp] = su;
    __syncthreads();
    su = red[0] + red[1] + red[2] + red[3];
    if (t < len) w_sh[t] = e / su;
    __syncthreads();

    const int d = blockIdx.y * 128 + t;
    const float* Xp = bert + ((size_t)b * Sn + 3) * Dn + d;
    float a0 = 0.f, a1 = 0.f, a2 = 0.f, a3 = 0.f;
    int s = 0;
    const int nn = len & ~3;
    for (; s < nn; s += 4) {
        a0 += w_sh[s]     * Xp[(size_t)(s)     * Dn];
        a1 += w_sh[s + 1] * Xp[(size_t)(s + 1) * Dn];
        a2 += w_sh[s + 2] * Xp[(size_t)(s + 2) * Dn];
        a3 += w_sh[s + 3] * Xp[(size_t)(s + 3) * Dn];
    }
    for (; s < len; ++s) a0 += w_sh[s] * Xp[(size_t)s * Dn];
    g_feats[(size_t)b * K2 + d] = (a0 + a1) + (a2 + a3);
}

// ---------------------------------------------------------------------------
// kB: split-bf16 tensor-core GEMM (HMMA m16n8k16), split-K partials.
// C = F[256x1536] @ W[768x1536]^T, both K-contiguous (row.col mma).
// Block: 128(M) x 64(N), BK=32, 256 thr = 8 warps (4x2), warp tile 32x32.
// Emulated fp32: a*b ~= ah*bh + ah*bl + al*bh  (bf16 hi/lo split).
// ---------------------------------------------------------------------------
#define LDK 40   // padded row length in bf16 (80B rows: conflict-free ldmatrix)

__device__ __forceinline__ void mma_bf16(
    float* c, const unsigned* a, const unsigned* b)
{
    asm volatile(
        "mma.sync.aligned.m16n8k16.row.col.f32.bf16.bf16.f32 "
        "{%0,%1,%2,%3}, {%4,%5,%6,%7}, {%8,%9}, {%0,%1,%2,%3};"
        : "+f"(c[0]), "+f"(c[1]), "+f"(c[2]), "+f"(c[3])
        : "r"(a[0]), "r"(a[1]), "r"(a[2]), "r"(a[3]), "r"(b[0]), "r"(b[1]));
}

__device__ __forceinline__ void ldsm4(unsigned* r, unsigned addr)
{
    asm volatile("ldmatrix.sync.aligned.m8n8.x4.shared.b16 {%0,%1,%2,%3}, [%4];"
                 : "=r"(r[0]), "=r"(r[1]), "=r"(r[2]), "=r"(r[3]) : "r"(addr));
}

__global__ __launch_bounds__(256) void kB(const float* __restrict__ Wd)
{
    __shared__ __nv_bfloat16 Ah_s[128 * LDK];
    __shared__ __nv_bfloat16 Al_s[128 * LDK];
    __shared__ __nv_bfloat16 Bh_s[64 * LDK];
    __shared__ __nv_bfloat16 Bl_s[64 * LDK];

    const int t = threadIdx.x;
    const int warp = t >> 5, lane = t & 31;
    const int bm = blockIdx.y * 128;
    const int bn = blockIdx.x * 64;
    const int kbase = blockIdx.z * KCH;

    const int wm = warp >> 1;          // 0..3 -> m offset 32*wm
    const int wn = warp & 1;           // 0..1 -> n offset 32*wn

    float acc[2][4][4] = {};

    const unsigned a_base = (unsigned)__cvta_generic_to_shared(Ah_s);
    const unsigned al_base = (unsigned)__cvta_generic_to_shared(Al_s);
    const unsigned b_base = (unsigned)__cvta_generic_to_shared(Bh_s);
    const unsigned bl_base = (unsigned)__cvta_generic_to_shared(Bl_s);

    for (int kt = 0; kt < KCH; kt += 32) {
        const int kg = kbase + kt;
        __syncthreads();
        // fill A tile: 128 rows x 32 k  (4 float4 per thread)
        #pragma unroll
        for (int i = 0; i < 4; ++i) {
            const int idx = t + i * 256;            // 0..1023
            const int m = idx >> 3, kq = (idx & 7) * 4;
            const float4 v = *(const float4*)&g_feats[(size_t)(bm + m) * K2 + kg + kq];
            __nv_bfloat16 h0 = __float2bfloat16(v.x), h1 = __float2bfloat16(v.y);
            __nv_bfloat16 h2 = __float2bfloat16(v.z), h3 = __float2bfloat16(v.w);
            __nv_bfloat16* ph = &Ah_s[m * LDK + kq];
            ph[0] = h0; ph[1] = h1; ph[2] = h2; ph[3] = h3;
            __nv_bfloat16* pl = &Al_s[m * LDK + kq];
            pl[0] = __float2bfloat16(v.x - __bfloat162float(h0));
            pl[1] = __float2bfloat16(v.y - __bfloat162float(h1));
            pl[2] = __float2bfloat16(v.z - __bfloat162float(h2));
            pl[3] = __float2bfloat16(v.w - __bfloat162float(h3));
        }
        // fill B tile: 64 rows x 32 k  (2 float4 per thread)
        #pragma unroll
        for (int i = 0; i < 2; ++i) {
            const int idx = t + i * 256;            // 0..511
            const int n = idx >> 3, kq = (idx & 7) * 4;
            const float4 v = *(const float4*)&Wd[(size_t)(bn + n) * K2 + kg + kq];
            __nv_bfloat16 h0 = __float2bfloat16(v.x), h1 = __float2bfloat16(v.y);
            __nv_bfloat16 h2 = __float2bfloat16(v.z), h3 = __float2bfloat16(v.w);
            __nv_bfloat16* ph = &Bh_s[n * LDK + kq];
            ph[0] = h0; ph[1] = h1; ph[2] = h2; ph[3] = h3;
            __nv_bfloat16* pl = &Bl_s[n * LDK + kq];
            pl[0] = __float2bfloat16(v.x - __bfloat162float(h0));
            pl[1] = __float2bfloat16(v.y - __bfloat162float(h1));
            pl[2] = __float2bfloat16(v.z - __bfloat162float(h2));
            pl[3] = __float2bfloat16(v.w - __bfloat162float(h3));
        }
        __syncthreads();

        #pragma unroll
        for (int kk = 0; kk < 32; kk += 16) {
            // A frags: rows wm*32 + tm*16, lanes 0-15 rows, 16-31 rows @k+8
            unsigned Ah[2][4], Al[2][4];
            #pragma unroll
            for (int tm = 0; tm < 2; ++tm) {
                const unsigned off =
                    (unsigned)(((wm * 32 + tm * 16 + (lane & 15)) * LDK
                               + kk + (lane >> 4) * 8) * 2);
                ldsm4(Ah[tm], a_base + off);
                ldsm4(Al[tm], al_base + off);
            }
            // B frags: 2 x ldmatrix.x4, each yields two n8 tiles (b0,b1 each)
            unsigned Bh[4][2], Bl[4][2];
            #pragma unroll
            for (int bj = 0; bj < 2; ++bj) {
                const int quad = lane >> 3, l8 = lane & 7;
                const int n = wn * 32 + bj * 16 + (quad >> 1) * 8 + l8;
                const int k = kk + (quad & 1) * 8;
                const unsigned off = (unsigned)((n * LDK + k) * 2);
                unsigned r[4];
                ldsm4(r, b_base + off);
                Bh[bj * 2][0] = r[0]; Bh[bj * 2][1] = r[1];
                Bh[bj * 2 + 1][0] = r[2]; Bh[bj * 2 + 1][1] = r[3];
                ldsm4(r, bl_base + off);
                Bl[bj * 2][0] = r[0]; Bl[bj * 2][1] = r[1];
                Bl[bj * 2 + 1][0] = r[2]; Bl[bj * 2 + 1][1] = r[3];
            }
            #pragma unroll
            for (int tm = 0; tm < 2; ++tm)
                #pragma unroll
                for (int tn = 0; tn < 4; ++tn) {
                    mma_bf16(acc[tm][tn], Ah[tm], Bh[tn]);
                    mma_bf16(acc[tm][tn], Ah[tm], Bl[tn]);
                    mma_bf16(acc[tm][tn], Al[tm], Bh[tn]);
                }
        }
    }

    float* P = g_part[blockIdx.z];
    const int r0 = bm + wm * 32 + (lane >> 2);
    const int c0 = bn + wn * 32 + (lane & 3) * 2;
    #pragma unroll
    for (int tm = 0; tm < 2; ++tm)
        #pragma unroll
        for (int tn = 0; tn < 4; ++tn) {
            const int r = r0 + tm * 16;
            const int c = c0 + tn * 8;
            *(float2*)&P[(size_t)r * Dn + c]       = make_float2(acc[tm][tn][0], acc[tm][tn][1]);
            *(float2*)&P[(size_t)(r + 8) * Dn + c] = make_float2(acc[tm][tn][2], acc[tm][tn][3]);
        }
}

// kB2: reduce split-K partials + bias + tanh (deterministic order)
__global__ __launch_bounds__(256) void kB2(const float* __restrict__ bd)
{
    const int i = blockIdx.x * 256 + threadIdx.x;
    float s = bd[i % Dn];
    #pragma unroll
    for (int p = 0; p < KSPLIT; ++p) s += g_part[p][i];
    g_h[i] = tanhf(s);
}

// ---------------------------------------------------------------------------
// kC: 21 sparse decoder rows + label-group mixes
// ---------------------------------------------------------------------------
__global__ __launch_bounds__(256) void kC(
    const float* __restrict__ dec_w,
    const float* __restrict__ dec_b,
    const float* __restrict__ w0,
    const float* __restrict__ w1,
    const float* __restrict__ w2,
    float*       __restrict__ out)
{
    const int b = blockIdx.x;
    const int t = threadIdx.x;
    const int warp = t >> 5, lane = t & 31;

    __shared__ float hs[Dn];
    __shared__ float probs[21];

    #pragma unroll
    for (int j = 0; j < 3; ++j) hs[t + j * 256] = g_h[(size_t)b * Dn + t + j * 256];
    __syncthreads();

    for (int j = warp; j < 21; j += 8) {
        const int v = c_ids[j];
        const float* row = dec_w + (size_t)v * Dn;
        float s = 0.f;
        for (int d = lane * 4; d < Dn; d += 128) {
            const float4 h4 = *(const float4*)&hs[d];
            const float4 r4 = *(const float4*)&row[d];
            s += h4.x * r4.x + h4.y * r4.y + h4.z * r4.z + h4.w * r4.w;
        }
        #pragma unroll
        for (int o = 16; o > 0; o >>= 1) s += __shfl_xor_sync(0xffffffffu, s, o);
        if (lane == 0) probs[j] = tanhf(s + dec_b[v]);
    }
    __syncthreads();

    if (t < 6) {
        const int o = t / 3, g = t % 3;
        const float* w = (g == 0) ? w0 : (g == 1) ? w1 : w2;
        const int off = (g == 0) ? 0 : (g == 1) ? 8 : 14;
        const int n   = (g == 0) ? 8 : (g == 1) ? 6 : 7;
        float s = 0.f;
        for (int j = 0; j < n; ++j) s += probs[off + j] * w[o * n + j];
        out[2 * Bn + b * 6 + o * 3 + g] = s;
    }
}

// ---------------------------------------------------------------------------
extern "C" void kernel_launch(void* const* d_in, const int* in_sizes, int n_in,
                              void* d_out, int out_size)
{
    const float* bert    = (const float*)d_in[0];
    const int*   ids     = (const int*)  d_in[1];
    const int*   length  = (const int*)  d_in[2];
    const float* senti_w = (const float*)d_in[3];
    const float* senti_b = (const float*)d_in[4];
    const float* dense_w = (const float*)d_in[5];
    const float* dense_b = (const float*)d_in[6];
    const float* dec_w   = (const float*)d_in[7];
    const float* dec_b   = (const float*)d_in[8];
    const float* w0      = (const float*)d_in[9];
    const float* w1      = (const float*)d_in[10];
    const float* w2      = (const float*)d_in[11];
    float* out = (float*)d_out;

    kA0<<<Bn, 128>>>(bert, ids, senti_w, senti_b, out);
    kA1<<<dim3(Bn, 16), 256>>>(bert, length);
    kA2<<<dim3(Bn, 6), 128>>>(bert, length);
    kB <<<dim3(Dn / 64, Bn / 128, KSPLIT), 256>>>(dense_w);
    kB2<<<(Bn * Dn) / 256, 256>>>(dense_b);
    kC <<<Bn, 256>>>(dec_w, dec_b, w0, w1, w2, out);
}

// round 4
// speedup vs baseline: 1.9261x; 1.0224x over previous
#include <cuda_runtime.h>
#include <cuda_bf16.h>
#include <math.h>

#define Bn 256
#define Sn 128
#define Dn 768
#define K2 1536
#define MASK_ID 103
#define KSPLIT 8
#define KCH (K2 / KSPLIT)   // 192
#define NIT (KCH / 32)      // 6

// Scratch (__device__ globals; no allocs allowed)
__device__ float g_ml[Bn * Dn];                 // mask_logits per batch (fp32)
__device__ float g_sc[Bn * Sn];                 // raw scores
__device__ __nv_bfloat16 g_featsH[Bn * K2];     // feats bf16 hi
__device__ __nv_bfloat16 g_featsL[Bn * K2];     // feats bf16 lo
__device__ __nv_bfloat16 g_WH[Dn * K2];         // dense_w bf16 hi
__device__ __nv_bfloat16 g_WL[Dn * K2];         // dense_w bf16 lo
__device__ float g_part[KSPLIT][Bn * Dn];       // split-K partials

static __device__ const int c_ids[21] = {
    2307, 2204, 3835, 2157, 6581, 2986, 5151, 3893,
    7929, 24791, 8699, 4257, 16021, 6623,
    6659, 2919, 11771, 3532, 11325, 4997, 13135
};

__device__ __forceinline__ void split_store(
    __nv_bfloat16* ph, __nv_bfloat16* pl, float v)
{
    const __nv_bfloat16 h = __float2bfloat16(v);
    *ph = h;
    *pl = __float2bfloat16(v - __bfloat162float(h));
}

// ---------------------------------------------------------------------------
// kW: split dense_w into bf16 hi/lo (once per call)
// ---------------------------------------------------------------------------
__global__ __launch_bounds__(256) void kW(const float* __restrict__ Wd)
{
    const int i = (blockIdx.x * 256 + threadIdx.x) * 4;
    const float4 v = *(const float4*)&Wd[i];
    __nv_bfloat16 h[4], l[4];
    h[0] = __float2bfloat16(v.x); l[0] = __float2bfloat16(v.x - __bfloat162float(h[0]));
    h[1] = __float2bfloat16(v.y); l[1] = __float2bfloat16(v.y - __bfloat162float(h[1]));
    h[2] = __float2bfloat16(v.z); l[2] = __float2bfloat16(v.z - __bfloat162float(h[2]));
    h[3] = __float2bfloat16(v.w); l[3] = __float2bfloat16(v.w - __bfloat162float(h[3]));
    *(uint2*)&g_WH[i] = *(uint2*)h;
    *(uint2*)&g_WL[i] = *(uint2*)l;
}

// ---------------------------------------------------------------------------
// kA0: mask find, mask_logits copy (fp32 + bf16 split), category head
// ---------------------------------------------------------------------------
__global__ __launch_bounds__(128) void kA0(
    const float* __restrict__ bert,
    const int*   __restrict__ ids,
    const float* __restrict__ senti_w,
    const float* __restrict__ senti_b,
    float*       __restrict__ out)
{
    const int b = blockIdx.x;
    const int t = threadIdx.x;
    const int warp = t >> 5, lane = t & 31;
    __shared__ int mp_s;

    if (ids[b * Sn + t] == MASK_ID) mp_s = t;
    __syncthreads();
    const int mp = mp_s;
    const float* X = bert + (size_t)b * Sn * Dn;

    #pragma unroll
    for (int j = 0; j < 6; ++j) {
        const int d = t + j * 128;
        const float v = X[(size_t)mp * Dn + d];
        g_ml[(size_t)b * Dn + d] = v;
        split_store(&g_featsH[(size_t)b * K2 + Dn + d],
                    &g_featsL[(size_t)b * K2 + Dn + d], v);
    }

    if (warp < 2) {
        float s = 0.f;
        for (int d = lane * 4; d < Dn; d += 128) {
            const float4 x = *(const float4*)&X[d];
            const float4 w = *(const float4*)&senti_w[warp * Dn + d];
            s += x.x * w.x + x.y * w.y + x.z * w.z + x.w * w.w;
        }
        #pragma unroll
        for (int o = 16; o > 0; o >>= 1) s += __shfl_xor_sync(0xffffffffu, s, o);
        if (lane == 0) out[b * 2 + warp] = s + senti_b[warp];
    }
}

// ---------------------------------------------------------------------------
// kA1: scores_raw[b,s] = dot(bert[b,s,:], ml[b,:]) for valid rows
// ---------------------------------------------------------------------------
__global__ __launch_bounds__(256) void kA1(
    const float* __restrict__ bert,
    const int*   __restrict__ length)
{
    const int b = blockIdx.x;
    const int len = length[b];
    const int s0 = blockIdx.y * 8;
    if (s0 >= 3 + len) return;

    const int t = threadIdx.x;
    const int warp = t >> 5, lane = t & 31;

    __shared__ float ml[Dn];
    #pragma unroll
    for (int j = 0; j < 3; ++j) ml[t + j * 256] = g_ml[(size_t)b * Dn + t + j * 256];
    __syncthreads();

    const int s = s0 + warp;
    if (s < 3 || s >= 3 + len) return;

    const float* row = bert + ((size_t)b * Sn + s) * Dn;
    float acc = 0.f;
    #pragma unroll
    for (int j = 0; j < 6; ++j) {
        const int d = j * 128 + lane * 4;
        const float4 x = *(const float4*)&row[d];
        const float4 m = *(const float4*)&ml[d];
        acc += x.x * m.x + x.y * m.y + x.z * m.z + x.w * m.w;
    }
    #pragma unroll
    for (int o = 16; o > 0; o >>= 1) acc += __shfl_xor_sync(0xffffffffu, acc, o);
    if (lane == 0) g_sc[b * Sn + s] = acc;
}

// ---------------------------------------------------------------------------
// kA2: softmax (tiny, recomputed) + attention pool -> bf16 split feats
// ---------------------------------------------------------------------------
__global__ __launch_bounds__(128) void kA2(
    const float* __restrict__ bert,
    const int*   __restrict__ length)
{
    const int b = blockIdx.x;
    const int t = threadIdx.x;
    const int warp = t >> 5, lane = t & 31;
    const int len = length[b];

    __shared__ float w_sh[112];
    __shared__ float red[4];

    float v = (t < len) ? g_sc[b * Sn + 3 + t] : -INFINITY;
    float m = v;
    #pragma unroll
    for (int o = 16; o > 0; o >>= 1) m = fmaxf(m, __shfl_xor_sync(0xffffffffu, m, o));
    if (lane == 0) red[warp] = m;
    __syncthreads();
    m = fmaxf(fmaxf(red[0], red[1]), fmaxf(red[2], red[3]));

    float e = (t < len) ? __expf(v - m) : 0.f;
    float su = e;
    #pragma unroll
    for (int o = 16; o > 0; o >>= 1) su += __shfl_xor_sync(0xffffffffu, su, o);
    __syncthreads();
    if (lane == 0) red[warp] = su;
    __syncthreads();
    su = red[0] + red[1] + red[2] + red[3];
    if (t < len) w_sh[t] = e / su;
    __syncthreads();

    const int d = blockIdx.y * 128 + t;
    const float* Xp = bert + ((size_t)b * Sn + 3) * Dn + d;
    float a[8] = {};
    int s = 0;
    const int nn = len & ~7;
    for (; s < nn; s += 8) {
        #pragma unroll
        for (int u = 0; u < 8; ++u)
            a[u] += w_sh[s + u] * Xp[(size_t)(s + u) * Dn];
    }
    for (; s < len; ++s) a[0] += w_sh[s] * Xp[(size_t)s * Dn];
    const float att = ((a[0] + a[1]) + (a[2] + a[3])) + ((a[4] + a[5]) + (a[6] + a[7]));
    split_store(&g_featsH[(size_t)b * K2 + d], &g_featsL[(size_t)b * K2 + d], att);
}

// ---------------------------------------------------------------------------
// kB: pure bf16 tensor-core GEMM (split-bf16 emulated fp32), cp.async 2-stage.
// Block 64(M) x 64(N), BK=32, 128 thr = 4 warps (warp tile 32x32), KSPLIT=8.
// ---------------------------------------------------------------------------
#define LDK 40   // 80B rows, conflict-free ldmatrix

__device__ __forceinline__ void mma_bf16(
    float* c, const unsigned* a, const unsigned* b)
{
    asm volatile(
        "mma.sync.aligned.m16n8k16.row.col.f32.bf16.bf16.f32 "
        "{%0,%1,%2,%3}, {%4,%5,%6,%7}, {%8,%9}, {%0,%1,%2,%3};"
        : "+f"(c[0]), "+f"(c[1]), "+f"(c[2]), "+f"(c[3])
        : "r"(a[0]), "r"(a[1]), "r"(a[2]), "r"(a[3]), "r"(b[0]), "r"(b[1]));
}

__device__ __forceinline__ void ldsm4(unsigned* r, unsigned addr)
{
    asm volatile("ldmatrix.sync.aligned.m8n8.x4.shared.b16 {%0,%1,%2,%3}, [%4];"
                 : "=r"(r[0]), "=r"(r[1]), "=r"(r[2]), "=r"(r[3]) : "r"(addr));
}

__device__ __forceinline__ void cp16(void* dst, const void* src)
{
    const unsigned d = (unsigned)__cvta_generic_to_shared(dst);
    asm volatile("cp.async.ca.shared.global [%0], [%1], 16;" :: "r"(d), "l"(src));
}

__global__ __launch_bounds__(128) void kB()
{
    // [stage][tile: AH,AL,BH,BL][64*LDK]
    __shared__ __nv_bfloat16 smem[2][4][64 * LDK];

    const int t = threadIdx.x;
    const int warp = t >> 5, lane = t & 31;
    const int bn = blockIdx.x * 64;
    const int bm = blockIdx.y * 64;
    const int kbase = blockIdx.z * KCH;
    const int wm = warp & 1, wn = warp >> 1;

    float acc[2][4][4] = {};

    const int row = t >> 2;            // 0..31 (x2 halves below)
    const int cq  = (t & 3) * 8;       // bf16 offset of 16B chunk

    #define ISSUE(it, stg) do {                                                   \
        const int kg = kbase + (it) * 32;                                          \
        _Pragma("unroll")                                                          \
        for (int i = 0; i < 2; ++i) {                                              \
            const int r = row + i * 32;                                            \
            cp16(&smem[stg][0][r * LDK + cq], &g_featsH[(size_t)(bm + r) * K2 + kg + cq]); \
            cp16(&smem[stg][1][r * LDK + cq], &g_featsL[(size_t)(bm + r) * K2 + kg + cq]); \
            cp16(&smem[stg][2][r * LDK + cq], &g_WH[(size_t)(bn + r) * K2 + kg + cq]);     \
            cp16(&smem[stg][3][r * LDK + cq], &g_WL[(size_t)(bn + r) * K2 + kg + cq]);     \
        }                                                                          \
        asm volatile("cp.async.commit_group;");                                    \
    } while (0)

    ISSUE(0, 0);

    for (int it = 0; it < NIT; ++it) {
        const int stg = it & 1;
        if (it + 1 < NIT) {
            ISSUE(it + 1, stg ^ 1);
            asm volatile("cp.async.wait_group 1;");
        } else {
            asm volatile("cp.async.wait_group 0;");
        }
        __syncthreads();

        const unsigned ah_b = (unsigned)__cvta_generic_to_shared(smem[stg][0]);
        const unsigned al_b = (unsigned)__cvta_generic_to_shared(smem[stg][1]);
        const unsigned bh_b = (unsigned)__cvta_generic_to_shared(smem[stg][2]);
        const unsigned bl_b = (unsigned)__cvta_generic_to_shared(smem[stg][3]);

        #pragma unroll
        for (int kk = 0; kk < 32; kk += 16) {
            unsigned Ah[2][4], Al[2][4];
            #pragma unroll
            for (int tm = 0; tm < 2; ++tm) {
                const unsigned off =
                    (unsigned)(((wm * 32 + tm * 16 + (lane & 15)) * LDK
                               + kk + (lane >> 4) * 8) * 2);
                ldsm4(Ah[tm], ah_b + off);
                ldsm4(Al[tm], al_b + off);
            }
            unsigned Bh[4][2], Bl[4][2];
            #pragma unroll
            for (int bj = 0; bj < 2; ++bj) {
                const int quad = lane >> 3, l8 = lane & 7;
                const int n = wn * 32 + bj * 16 + (quad >> 1) * 8 + l8;
                const int k = kk + (quad & 1) * 8;
                const unsigned off = (unsigned)((n * LDK + k) * 2);
                unsigned r4[4];
                ldsm4(r4, bh_b + off);
                Bh[bj * 2][0] = r4[0]; Bh[bj * 2][1] = r4[1];
                Bh[bj * 2 + 1][0] = r4[2]; Bh[bj * 2 + 1][1] = r4[3];
                ldsm4(r4, bl_b + off);
                Bl[bj * 2][0] = r4[0]; Bl[bj * 2][1] = r4[1];
                Bl[bj * 2 + 1][0] = r4[2]; Bl[bj * 2 + 1][1] = r4[3];
            }
            #pragma unroll
            for (int tm = 0; tm < 2; ++tm)
                #pragma unroll
                for (int tn = 0; tn < 4; ++tn) {
                    mma_bf16(acc[tm][tn], Ah[tm], Bh[tn]);
                    mma_bf16(acc[tm][tn], Ah[tm], Bl[tn]);
                    mma_bf16(acc[tm][tn], Al[tm], Bh[tn]);
                }
        }
        __syncthreads();
    }

    float* P = g_part[blockIdx.z];
    const int r0 = bm + wm * 32 + (lane >> 2);
    const int c0 = bn + wn * 32 + (lane & 3) * 2;
    #pragma unroll
    for (int tm = 0; tm < 2; ++tm)
        #pragma unroll
        for (int tn = 0; tn < 4; ++tn) {
            const int r = r0 + tm * 16;
            const int c = c0 + tn * 8;
            *(float2*)&P[(size_t)r * Dn + c]       = make_float2(acc[tm][tn][0], acc[tm][tn][1]);
            *(float2*)&P[(size_t)(r + 8) * Dn + c] = make_float2(acc[tm][tn][2], acc[tm][tn][3]);
        }
}

// ---------------------------------------------------------------------------
// kC: fused split-K reduce + bias + tanh, then 21 decoder rows + mixes
// ---------------------------------------------------------------------------
__global__ __launch_bounds__(256) void kC(
    const float* __restrict__ dense_b,
    const float* __restrict__ dec_w,
    const float* __restrict__ dec_b,
    const float* __restrict__ w0,
    const float* __restrict__ w1,
    const float* __restrict__ w2,
    float*       __restrict__ out)
{
    const int b = blockIdx.x;
    const int t = threadIdx.x;
    const int warp = t >> 5, lane = t & 31;

    __shared__ float hs[Dn];
    __shared__ float probs[21];

    #pragma unroll
    for (int j = 0; j < 3; ++j) {
        const int d = t + j * 256;
        float s = dense_b[d];
        #pragma unroll
        for (int p = 0; p < KSPLIT; ++p) s += g_part[p][(size_t)b * Dn + d];
        hs[d] = tanhf(s);
    }
    __syncthreads();

    for (int j = warp; j < 21; j += 8) {
        const int v = c_ids[j];
        const float* rw = dec_w + (size_t)v * Dn;
        float s = 0.f;
        for (int d = lane * 4; d < Dn; d += 128) {
            const float4 h4 = *(const float4*)&hs[d];
            const float4 r4 = *(const float4*)&rw[d];
            s += h4.x * r4.x + h4.y * r4.y + h4.z * r4.z + h4.w * r4.w;
        }
        #pragma unroll
        for (int o = 16; o > 0; o >>= 1) s += __shfl_xor_sync(0xffffffffu, s, o);
        if (lane == 0) probs[j] = tanhf(s + dec_b[v]);
    }
    __syncthreads();

    if (t < 6) {
        const int o = t / 3, g = t % 3;
        const float* w = (g == 0) ? w0 : (g == 1) ? w1 : w2;
        const int off = (g == 0) ? 0 : (g == 1) ? 8 : 14;
        const int n   = (g == 0) ? 8 : (g == 1) ? 6 : 7;
        float s = 0.f;
        for (int j = 0; j < n; ++j) s += probs[off + j] * w[o * n + j];
        out[2 * Bn + b * 6 + o * 3 + g] = s;
    }
}

// ---------------------------------------------------------------------------
extern "C" void kernel_launch(void* const* d_in, const int* in_sizes, int n_in,
                              void* d_out, int out_size)
{
    const float* bert    = (const float*)d_in[0];
    const int*   ids     = (const int*)  d_in[1];
    const int*   length  = (const int*)  d_in[2];
    const float* senti_w = (const float*)d_in[3];
    const float* senti_b = (const float*)d_in[4];
    const float* dense_w = (const float*)d_in[5];
    const float* dense_b = (const float*)d_in[6];
    const float* dec_w   = (const float*)d_in[7];
    const float* dec_b   = (const float*)d_in[8];
    const float* w0      = (const float*)d_in[9];
    const float* w1      = (const float*)d_in[10];
    const float* w2      = (const float*)d_in[11];
    float* out = (float*)d_out;

    kW <<<(Dn * K2) / (256 * 4), 256>>>(dense_w);
    kA0<<<Bn, 128>>>(bert, ids, senti_w, senti_b, out);
    kA1<<<dim3(Bn, 16), 256>>>(bert, length);
    kA2<<<dim3(Bn, 6), 128>>>(bert, length);
    kB <<<dim3(Dn / 64, Bn / 64, KSPLIT), 128>>>();
    kC <<<Bn, 256>>>(dense_b, dec_w, dec_b, w0, w1, w2, out);
}